// round 1
// baseline (speedup 1.0000x reference)
#include <cuda_runtime.h>

#define DD 512
#define NN 256
#define PP 256
#define LL 2048

// ---------------- scratch (static device globals; no allocation) ----------------
__device__ float g_V[LL * DD];           // V[t][d], column (per-t) contiguous: V[t*512+d]  (4 MB)
__device__ float g_T0[1024 * DD];        // tree ping buffer (2 MB)
__device__ float g_T1[1024 * DD];        // tree pong buffer (2 MB)
__device__ float g_Apow[10 * DD * DD];   // A^2, A^4, ..., A^1024 (10 MB)
__device__ float g_Q0[8 * DD];
__device__ float g_Q1[8 * DD];
__device__ float g_S[17 * 24 * PP];      // S_l[j][p]
__device__ float g_wv[306 * PP];         // weight vectors for the big M contraction

// ---------------- generic strided SGEMM: C = A*B (+ Add), bounds on N only ------
// M assumed multiple of 64, K multiple of 16 (true for all call sites).
__global__ void sgemm_k(const float* __restrict__ A, int Ars, int Acs,
                        const float* __restrict__ B, int Bks, int Bjs,
                        const float* __restrict__ Add, int Adis, int Adjs,
                        float* __restrict__ C, int Cis, int Cjs,
                        int M, int N, int K)
{
    __shared__ float As[64][17];   // As[m][kk]
    __shared__ float Bs[16][65];   // Bs[kk][nj]

    const int bm = blockIdx.y * 64;
    const int bn = blockIdx.x * 64;
    const int tid = threadIdx.x;
    const int tx = tid & 15;
    const int ty = tid >> 4;

    float acc[4][4] = {};

    for (int k0 = 0; k0 < K; k0 += 16) {
        // A tile: kk fastest (Acs==1 in all uses -> coalesced)
        #pragma unroll
        for (int i = tid; i < 64 * 16; i += 256) {
            int kk = i & 15, m = i >> 4;
            As[m][kk] = A[(bm + m) * Ars + (k0 + kk) * Acs];
        }
        // B tile: pick coalesced direction based on which stride is unit
        if (Bks == 1) {
            #pragma unroll
            for (int i = tid; i < 16 * 64; i += 256) {
                int kk = i & 15, nj = i >> 4;
                int gn = bn + nj;
                Bs[kk][nj] = (gn < N) ? B[(k0 + kk) * Bks + gn * Bjs] : 0.f;
            }
        } else {
            #pragma unroll
            for (int i = tid; i < 16 * 64; i += 256) {
                int nj = i & 63, kk = i >> 6;
                int gn = bn + nj;
                Bs[kk][nj] = (gn < N) ? B[(k0 + kk) * Bks + gn * Bjs] : 0.f;
            }
        }
        __syncthreads();

        #pragma unroll
        for (int kk = 0; kk < 16; kk++) {
            float a[4], b[4];
            #pragma unroll
            for (int i = 0; i < 4; i++) a[i] = As[ty * 4 + i][kk];
            #pragma unroll
            for (int j = 0; j < 4; j++) b[j] = Bs[kk][tx * 4 + j];
            #pragma unroll
            for (int i = 0; i < 4; i++)
                #pragma unroll
                for (int j = 0; j < 4; j++)
                    acc[i][j] = fmaf(a[i], b[j], acc[i][j]);
        }
        __syncthreads();
    }

    #pragma unroll
    for (int i = 0; i < 4; i++) {
        int gm = bm + ty * 4 + i;
        #pragma unroll
        for (int j = 0; j < 4; j++) {
            int gn = bn + tx * 4 + j;
            if (gn < N) {
                float v = acc[i][j];
                if (Add) v += Add[gm * Adis + gn * Adjs];
                C[gm * Cis + gn * Cjs] = v;
            }
        }
    }
}

// ---------------- y_nat / pred: out[row] = ylast[p] + C_row . x ------------------
__global__ void ynat_pred_kernel(const float* __restrict__ Cm, const float* __restrict__ ylast,
                                 const float* __restrict__ s, const float* __restrict__ q,
                                 float* __restrict__ out)
{
    int row = blockIdx.x;          // 0..511 ; <256 -> y_nat, else pred
    int p = row & 255;
    bool isPred = row >= 256;
    const float* cr = Cm + p * 512;
    float acc = 0.f;
    for (int d = threadIdx.x; d < 512; d += 128) {
        float x = isPred ? (q[d] - s[d]) : (-s[d]);
        acc += cr[d] * x;
    }
    __shared__ float sd[128];
    sd[threadIdx.x] = acc;
    __syncthreads();
    for (int st = 64; st > 0; st >>= 1) {
        if (threadIdx.x < st) sd[threadIdx.x] += sd[threadIdx.x + st];
        __syncthreads();
    }
    if (threadIdx.x == 0) out[row] = ylast[p] + sd[0];
}

// ---------------- S_l[j][p] = sum_k phi[k,l] * Yrev[2+j+k][p] --------------------
__global__ void s_kernel(const float* __restrict__ phi, const float* __restrict__ ynh,
                         float* __restrict__ S)
{
    int l = blockIdx.x / 24;
    int j = blockIdx.x % 24;
    int p = threadIdx.x;
    float acc = 0.f;
    #pragma unroll
    for (int k = 0; k < 25; k++)
        acc += phi[k * 17 + l] * ynh[(2047 - (2 + j + k)) * 256 + p];
    S[blockIdx.x * 256 + p] = acc;
}

// ---------------- build the 306 weight vectors ----------------------------------
__global__ void wv_kernel(const float* __restrict__ ynh, const float* __restrict__ S,
                          const float* __restrict__ phi, const float* __restrict__ phit,
                          const float* __restrict__ sig, const float* __restrict__ lam,
                          float* __restrict__ wv)
{
    int b = blockIdx.x, p = threadIdx.x;
    float v;
    if (b == 0) {
        v = ynh[2047 * 256 + p];                                  // Yrev[0] for M_bar[0]
    } else if (b < 17) {
        int i = b - 1;
        float lam4 = sqrtf(sqrtf(lam[i]));
        float acc = 0.f;
        #pragma unroll
        for (int j = 0; j < 24; j++)
            acc += phit[j * 16 + i] * ynh[(2047 - 1 - j) * 256 + p];
        v = lam4 * acc;                                           // for M_bar[1+i]
    } else {
        int bb = b - 17, ip = bb / 17, l = bb % 17;
        float s4 = sqrtf(sqrtf(sig[l]));
        if (ip == 0) {
            float acc = 0.f;
            #pragma unroll
            for (int k = 0; k < 25; k++)
                acc += phi[k * 17 + l] * ynh[(2047 - k) * 256 + p];
            v = s4 * acc;                                         // for M[0][l]
        } else {
            int i = ip - 1;
            float lam4 = sqrtf(sqrtf(lam[i]));
            float acc = 0.f;
            #pragma unroll
            for (int j = 0; j < 24; j++)
                acc += phit[j * 16 + i] * S[(l * 24 + j) * 256 + p];
            v = lam4 * s4 * acc;                                  // for M[1+i][l]
        }
    }
    wv[b * 256 + p] = v;
}

// ---------------- u_t[n] = sum over all 306 blocks of M_bar/M --------------------
__global__ void ut_kernel(const float* __restrict__ Mm, const float* __restrict__ Mbar,
                          const float* __restrict__ wv, float* __restrict__ out)
{
    int n = blockIdx.x, p = threadIdx.x;
    float acc = 0.f;
    #pragma unroll 4
    for (int b = 0; b < 17; b++)
        acc += Mbar[(b * 256 + n) * 256 + p] * wv[b * 256 + p];
    #pragma unroll 4
    for (int bb = 0; bb < 289; bb++)
        acc += Mm[(bb * 256 + n) * 256 + p] * wv[(17 + bb) * 256 + p];
    __shared__ float sd[256];
    sd[p] = acc;
    __syncthreads();
    for (int st = 128; st > 0; st >>= 1) {
        if (p < st) sd[p] += sd[p + st];
        __syncthreads();
    }
    if (p == 0) out[512 + n] = sd[0];
}

// =================================================================================
extern "C" void kernel_launch(void* const* d_in, const int* in_sizes, int n_in,
                              void* d_out, int out_size)
{
    const float* A    = (const float*)d_in[0];
    const float* Bm   = (const float*)d_in[1];
    const float* Cm   = (const float*)d_in[2];
    const float* Mm   = (const float*)d_in[3];
    const float* Mbar = (const float*)d_in[4];
    const float* sig  = (const float*)d_in[5];
    const float* phi  = (const float*)d_in[6];
    const float* lam  = (const float*)d_in[7];
    const float* phit = (const float*)d_in[8];
    const float* yh   = (const float*)d_in[9];
    const float* uh   = (const float*)d_in[10];
    const float* ynh  = (const float*)d_in[11];
    float* out = (float*)d_out;

    float *V, *T0, *T1, *Ap, *Q0, *Q1, *S, *wv;
    cudaGetSymbolAddress((void**)&V,  g_V);
    cudaGetSymbolAddress((void**)&T0, g_T0);
    cudaGetSymbolAddress((void**)&T1, g_T1);
    cudaGetSymbolAddress((void**)&Ap, g_Apow);
    cudaGetSymbolAddress((void**)&Q0, g_Q0);
    cudaGetSymbolAddress((void**)&Q1, g_Q1);
    cudaGetSymbolAddress((void**)&S,  g_S);
    cudaGetSymbolAddress((void**)&wv, g_wv);

    // ---- controller term (independent of the scan) ----
    s_kernel<<<17 * 24, 256>>>(phi, ynh, S);
    wv_kernel<<<306, 256>>>(ynh, S, phi, phit, sig, lam, wv);
    ut_kernel<<<256, 256>>>(Mm, Mbar, wv, out);

    // ---- V[t] = B @ u_t  (512 x 2048, K=256) ----
    {
        dim3 g((2048 + 63) / 64, 8);
        sgemm_k<<<g, 256>>>(Bm, 256, 1,  uh, 1, 256,  nullptr, 0, 0,
                            V, 1, 512,  512, 2048, 256);
    }

    // ---- tree reduction: s = sum_t A^(2047-t) v_t ----
    const float* Ak = A;
    float* tin  = V;
    float* tout = T0;
    int n = 1024;
    for (int k = 0; k < 11; k++) {
        // combine: w_m = A_k * v_{2m} + v_{2m+1}
        dim3 g((n + 63) / 64, 8);
        sgemm_k<<<g, 256>>>(Ak, 512, 1,  tin, 1, 1024,  tin + 512, 1, 1024,
                            tout, 1, 512,  512, n, 512);
        // square: A_{k+1} = A_k^2 (not needed after level 9)
        if (k < 10) {
            float* nxt = Ap + k * (512 * 512);
            dim3 gs(8, 8);
            sgemm_k<<<gs, 256>>>(Ak, 512, 1,  Ak, 512, 1,  nullptr, 0, 0,
                                 nxt, 512, 1,  512, 512, 512);
            Ak = nxt;
        }
        tin = tout;
        tout = (tout == T0) ? T1 : T0;
        n >>= 1;
    }
    const float* sv = tin;   // final state s (512)

    // ---- q = sum_{i<16} A^i z_i, z_i = V column (2047-i); mini-tree reusing A powers
    dim3 g1(1, 8);
    // level 0: w_m = z_{2m} + A * z_{2m+1}
    sgemm_k<<<g1, 256>>>(A, 512, 1,  V + 2046 * 512, 1, -1024,  V + 2047 * 512, 1, -1024,
                         Q0, 1, 512,  512, 8, 512);
    // level 1: A^2
    sgemm_k<<<g1, 256>>>(Ap + 0 * 512 * 512, 512, 1,  Q0 + 512, 1, 1024,  Q0, 1, 1024,
                         Q1, 1, 512,  512, 4, 512);
    // level 2: A^4
    sgemm_k<<<g1, 256>>>(Ap + 1 * 512 * 512, 512, 1,  Q1 + 512, 1, 1024,  Q1, 1, 1024,
                         Q0, 1, 512,  512, 2, 512);
    // level 3: A^8
    sgemm_k<<<g1, 256>>>(Ap + 2 * 512 * 512, 512, 1,  Q0 + 512, 1, 1024,  Q0, 1, 1024,
                         Q1, 1, 512,  512, 1, 512);

    // ---- y_nat = y_last - C s ; pred = y_last + C (q - s) ----
    ynat_pred_kernel<<<512, 128>>>(Cm, yh + 2047 * 256, sv, Q1, out);
}

// round 4
// speedup vs baseline: 5.6441x; 5.6441x over previous
#include <cuda_runtime.h>

#define DD 512

// ---------------- scratch (static device globals; no allocation) ----------------
__device__ float g_V[2048 * DD];          // V[t][d] at V[t*512+d]           (4 MB)
__device__ float g_T0[1024 * DD];         // tree ping                        (2 MB)
__device__ float g_T1[1024 * DD];         // tree pong                        (2 MB)
__device__ float g_Apow[10 * DD * DD];    // A^2 .. A^1024                   (10 MB)
__device__ float g_Q0[8 * DD];
__device__ float g_Q1[8 * DD];
__device__ float g_S[17 * 24 * 256];
__device__ float g_wv[306 * 256];
__device__ float g_partS[8 * DD * DD];    // split-K partials, squarings      (8 MB)
__device__ float g_partC[8 * DD * DD];    // split-K partials, combine        (8 MB)
__device__ float g_partQ[8 * DD * 8];     // split-K partials, Q chain

// ================= GEMM descriptor + device tile routine =========================
struct GemmDesc {
    const float* A; long long Ars;            // A[m*Ars + k], unit-k
    const float* B; long long Bks; long long Bjs; // Bks==1: B[k + n*Bjs]; else B[k*Bks + n]
    const float* Add; long long Adjs;         // Add[m + n*Adjs] (col-major), used when part==0
    float* C; long long Cis; long long Cjs;
    float* part; long long slab;              // if part: write partial z at part + z*slab
    int M, N, K;
    int gx, gy, gz;                           // logical grid of this piece
};

__device__ __forceinline__ void gemm_block(const GemmDesc& d, int r)
{
    __shared__ float As[2][16][68];
    __shared__ float Bs[2][16][68];

    const int bxg = r % d.gx;
    const int byg = (r / d.gx) % d.gy;
    const int z   = r / (d.gx * d.gy);

    const int tid = threadIdx.x;
    const int bm = byg * 64;
    const int bn = bxg * 64;
    const int Kc = d.K / d.gz;
    const int kbeg = z * Kc;
    const int ntiles = Kc >> 4;

    const int lk = (tid & 3) * 4;
    const int lm = tid >> 2;
    const int bkk = tid & 15;
    const int bn4 = (tid >> 4) * 4;
    const int tx = tid & 15, ty = tid >> 4;

    float4 ra, rb;
    const bool bok1 = (bn + lm) < d.N;
    const bool bok2 = (bn + bn4) < d.N;

    // ---- load tile 0 ----
    ra = *(const float4*)(d.A + (long long)(bm + lm) * d.Ars + (kbeg + lk));
    if (d.Bks == 1) {
        rb = bok1 ? *(const float4*)(d.B + (long long)(kbeg + lk)
                                         + (long long)(bn + lm) * d.Bjs)
                  : make_float4(0.f, 0.f, 0.f, 0.f);
    } else {
        rb = bok2 ? *(const float4*)(d.B + (long long)(kbeg + bkk) * d.Bks + bn + bn4)
                  : make_float4(0.f, 0.f, 0.f, 0.f);
    }
    {
        const float* rav = (const float*)&ra;
        const float* rbv = (const float*)&rb;
        #pragma unroll
        for (int j = 0; j < 4; j++) As[0][lk + j][lm] = rav[j];
        if (d.Bks == 1) {
            #pragma unroll
            for (int j = 0; j < 4; j++) Bs[0][lk + j][lm] = rbv[j];
        } else {
            #pragma unroll
            for (int j = 0; j < 4; j++) Bs[0][bkk][bn4 + j] = rbv[j];
        }
    }
    __syncthreads();

    float acc[4][4] = {};

    for (int t = 0; t < ntiles; t++) {
        int cur = t & 1;
        if (t + 1 < ntiles) {
            int k = kbeg + (t + 1) * 16;
            ra = *(const float4*)(d.A + (long long)(bm + lm) * d.Ars + k + lk);
            if (d.Bks == 1) {
                rb = bok1 ? *(const float4*)(d.B + (long long)(k + lk)
                                                 + (long long)(bn + lm) * d.Bjs)
                          : make_float4(0.f, 0.f, 0.f, 0.f);
            } else {
                rb = bok2 ? *(const float4*)(d.B + (long long)(k + bkk) * d.Bks + bn + bn4)
                          : make_float4(0.f, 0.f, 0.f, 0.f);
            }
        }
        #pragma unroll
        for (int kk = 0; kk < 16; kk++) {
            float4 a4 = *(const float4*)&As[cur][kk][ty * 4];
            float4 b4 = *(const float4*)&Bs[cur][kk][tx * 4];
            float av[4] = {a4.x, a4.y, a4.z, a4.w};
            float bv[4] = {b4.x, b4.y, b4.z, b4.w};
            #pragma unroll
            for (int i = 0; i < 4; i++)
                #pragma unroll
                for (int j = 0; j < 4; j++)
                    acc[i][j] = fmaf(av[i], bv[j], acc[i][j]);
        }
        if (t + 1 < ntiles) {
            __syncthreads();
            int nb = cur ^ 1;
            const float* rav = (const float*)&ra;
            const float* rbv = (const float*)&rb;
            #pragma unroll
            for (int j = 0; j < 4; j++) As[nb][lk + j][lm] = rav[j];
            if (d.Bks == 1) {
                #pragma unroll
                for (int j = 0; j < 4; j++) Bs[nb][lk + j][lm] = rbv[j];
            } else {
                #pragma unroll
                for (int j = 0; j < 4; j++) Bs[nb][bkk][bn4 + j] = rbv[j];
            }
            __syncthreads();
        }
    }

    float* outp = d.part ? (d.part + (long long)z * d.slab) : d.C;
    #pragma unroll
    for (int i = 0; i < 4; i++) {
        int gm = bm + ty * 4 + i;
        #pragma unroll
        for (int j = 0; j < 4; j++) {
            int gn = bn + tx * 4 + j;
            if (gn < d.N) {
                float v = acc[i][j];
                if (!d.part && d.Add) v += d.Add[gm + (long long)gn * d.Adjs];
                outp[(long long)gm * d.Cis + (long long)gn * d.Cjs] = v;
            }
        }
    }
}

// -------- up to 3 independent GEMM pieces in one launch --------------------------
__global__ __launch_bounds__(256)
void fused3_kernel(GemmDesc d0, GemmDesc d1, GemmDesc d2, int n0, int n1)
{
    int bx = blockIdx.x;
    if (bx < n0)             gemm_block(d0, bx);
    else if (bx < n0 + n1)   gemm_block(d1, bx - n0);
    else                     gemm_block(d2, bx - n0 - n1);
}

// ================= fused split-K reduce ==========================================
struct RedDesc {
    float* dst; const float* part;
    int len; int nz; long long slab;
    const float* Add; long long Adjs; int colMajor;
};

__device__ __forceinline__ void red_elem(const RedDesc& r, int g)
{
    int i = g * 4;
    float4 acc = *(const float4*)(r.part + i);
    for (int zz = 1; zz < r.nz; zz++) {
        float4 v = *(const float4*)(r.part + (long long)zz * r.slab + i);
        acc.x += v.x; acc.y += v.y; acc.z += v.z; acc.w += v.w;
    }
    if (r.Add && r.colMajor) {
        int gm = i & 511, gn = i >> 9;
        const float* ap = r.Add + gm + (long long)gn * r.Adjs;
        acc.x += ap[0]; acc.y += ap[1]; acc.z += ap[2]; acc.w += ap[3];
    }
    *(float4*)(r.dst + i) = acc;
}

__global__ __launch_bounds__(256)
void fusedred_kernel(RedDesc r0, RedDesc r1, RedDesc r2, int c0, int c1, int c2)
{
    int g = blockIdx.x * 256 + threadIdx.x;
    if (g < c0)                 red_elem(r0, g);
    else if (g < c0 + c1)       red_elem(r1, g - c0);
    else if (g < c0 + c1 + c2)  red_elem(r2, g - c0 - c1);
}

// ---------------- ut block (device) ----------------------------------------------
__device__ __forceinline__ void ut_block(const float* __restrict__ Mm,
                                         const float* __restrict__ Mbar,
                                         const float* __restrict__ wv,
                                         float* __restrict__ out, int n)
{
    int p = threadIdx.x;
    float acc = 0.f;
    #pragma unroll 4
    for (int b = 0; b < 17; b++)
        acc += Mbar[((long long)b * 256 + n) * 256 + p] * wv[b * 256 + p];
    #pragma unroll 4
    for (int bb = 0; bb < 289; bb++)
        acc += Mm[((long long)bb * 256 + n) * 256 + p] * wv[(17 + bb) * 256 + p];
    __shared__ float sd[256];
    sd[p] = acc;
    __syncthreads();
    for (int st = 128; st > 0; st >>= 1) {
        if (p < st) sd[p] += sd[p + st];
        __syncthreads();
    }
    if (p == 0) out[512 + n] = sd[0];
}

// -------- V GEMM + ut matvec in one launch ---------------------------------------
__global__ __launch_bounds__(256)
void vut_kernel(GemmDesc dv,
                const float* __restrict__ Mm, const float* __restrict__ Mbar,
                const float* __restrict__ wv, float* __restrict__ out)
{
    int bx = blockIdx.x;
    if (bx < 256) ut_block(Mm, Mbar, wv, out, bx);
    else          gemm_block(dv, bx - 256);
}

// ---------------- controller prep ------------------------------------------------
__global__ void s_kernel(const float* __restrict__ phi, const float* __restrict__ ynh,
                         float* __restrict__ S)
{
    int l = blockIdx.x / 24, j = blockIdx.x % 24, p = threadIdx.x;
    float acc = 0.f;
    #pragma unroll
    for (int k = 0; k < 25; k++)
        acc += phi[k * 17 + l] * ynh[(2047 - (2 + j + k)) * 256 + p];
    S[blockIdx.x * 256 + p] = acc;
}

__global__ void wv_kernel(const float* __restrict__ ynh, const float* __restrict__ S,
                          const float* __restrict__ phi, const float* __restrict__ phit,
                          const float* __restrict__ sig, const float* __restrict__ lam,
                          float* __restrict__ wv)
{
    int b = blockIdx.x, p = threadIdx.x;
    float v;
    if (b == 0) {
        v = ynh[2047 * 256 + p];
    } else if (b < 17) {
        int i = b - 1;
        float lam4 = sqrtf(sqrtf(lam[i]));
        float acc = 0.f;
        #pragma unroll
        for (int j = 0; j < 24; j++)
            acc += phit[j * 16 + i] * ynh[(2047 - 1 - j) * 256 + p];
        v = lam4 * acc;
    } else {
        int bb = b - 17, ip = bb / 17, l = bb % 17;
        float s4 = sqrtf(sqrtf(sig[l]));
        if (ip == 0) {
            float acc = 0.f;
            #pragma unroll
            for (int k = 0; k < 25; k++)
                acc += phi[k * 17 + l] * ynh[(2047 - k) * 256 + p];
            v = s4 * acc;
        } else {
            int i = ip - 1;
            float lam4 = sqrtf(sqrtf(lam[i]));
            float acc = 0.f;
            #pragma unroll
            for (int j = 0; j < 24; j++)
                acc += phit[j * 16 + i] * S[(l * 24 + j) * 256 + p];
            v = lam4 * s4 * acc;
        }
    }
    wv[b * 256 + p] = v;
}

// ---------------- y_nat / pred ---------------------------------------------------
__global__ void ynat_pred_kernel(const float* __restrict__ Cm, const float* __restrict__ ylast,
                                 const float* __restrict__ s, const float* __restrict__ q,
                                 float* __restrict__ out)
{
    int row = blockIdx.x;
    int p = row & 255;
    bool isPred = row >= 256;
    const float* cr = Cm + p * 512;
    float acc = 0.f;
    for (int d = threadIdx.x; d < 512; d += 128) {
        float x = isPred ? (q[d] - s[d]) : (-s[d]);
        acc += cr[d] * x;
    }
    __shared__ float sd[128];
    sd[threadIdx.x] = acc;
    __syncthreads();
    for (int st = 64; st > 0; st >>= 1) {
        if (threadIdx.x < st) sd[threadIdx.x] += sd[threadIdx.x + st];
        __syncthreads();
    }
    if (threadIdx.x == 0) out[row] = ylast[p] + sd[0];
}

// =================================================================================
extern "C" void kernel_launch(void* const* d_in, const int* in_sizes, int n_in,
                              void* d_out, int out_size)
{
    const float* A    = (const float*)d_in[0];
    const float* Bm   = (const float*)d_in[1];
    const float* Cm   = (const float*)d_in[2];
    const float* Mm   = (const float*)d_in[3];
    const float* Mbar = (const float*)d_in[4];
    const float* sig  = (const float*)d_in[5];
    const float* phi  = (const float*)d_in[6];
    const float* lam  = (const float*)d_in[7];
    const float* phit = (const float*)d_in[8];
    const float* yh   = (const float*)d_in[9];
    const float* uh   = (const float*)d_in[10];
    const float* ynh  = (const float*)d_in[11];
    float* out = (float*)d_out;

    float *V, *T0, *T1, *Ap, *Q0, *Q1, *S, *wv, *pS, *pC, *pQ;
    cudaGetSymbolAddress((void**)&V,  g_V);
    cudaGetSymbolAddress((void**)&T0, g_T0);
    cudaGetSymbolAddress((void**)&T1, g_T1);
    cudaGetSymbolAddress((void**)&Ap, g_Apow);
    cudaGetSymbolAddress((void**)&Q0, g_Q0);
    cudaGetSymbolAddress((void**)&Q1, g_Q1);
    cudaGetSymbolAddress((void**)&S,  g_S);
    cudaGetSymbolAddress((void**)&wv, g_wv);
    cudaGetSymbolAddress((void**)&pS, g_partS);
    cudaGetSymbolAddress((void**)&pC, g_partC);
    cudaGetSymbolAddress((void**)&pQ, g_partQ);

    GemmDesc dummy = {};
    dummy.gx = dummy.gy = dummy.gz = 1;
    RedDesc rdummy = {};

    // ---- controller prep (cheap, serial) ----
    s_kernel<<<17 * 24, 256>>>(phi, ynh, S);
    wv_kernel<<<306, 256>>>(ynh, S, phi, phit, sig, lam, wv);

    // ---- fused: ut matvec (256 blocks) || V = B @ U (512x2048, K=256; 256 blocks)
    {
        GemmDesc dv = {};
        dv.A = Bm; dv.Ars = 256;
        dv.B = uh; dv.Bks = 1; dv.Bjs = 256;
        dv.Add = nullptr; dv.Adjs = 0;
        dv.C = V; dv.Cis = 1; dv.Cjs = 512;
        dv.part = nullptr; dv.slab = 0;
        dv.M = 512; dv.N = 2048; dv.K = 256;
        dv.gx = 32; dv.gy = 8; dv.gz = 1;
        vut_kernel<<<256 + 32 * 8, 256>>>(dv, Mm, Mbar, wv, out);
    }

    // ---- fused tree levels: combine + squaring + Q-stage -------------------------
    const float* Ak = A;
    float* tin = V;
    float* tout = T0;
    int n = 1024;
    for (int k = 0; k < 11; k++) {
        GemmDesc g0 = dummy, g1 = dummy, g2 = dummy;
        RedDesc  r0 = rdummy, r1 = rdummy, r2 = rdummy;
        int n0 = 0, n1 = 0, n2 = 0;
        int c0 = 0, c1 = 0, c2 = 0;

        // piece 0: squaring A_{k+1} = A_k^2 (split-K 8)  [levels 0..9]
        if (k < 10) {
            float* nxt = Ap + (long long)k * (512 * 512);
            g0.A = Ak; g0.Ars = 512;
            g0.B = Ak; g0.Bks = 512; g0.Bjs = 0;
            g0.C = nxt; g0.Cis = 512; g0.Cjs = 1;
            g0.part = pS; g0.slab = 512 * 512;
            g0.M = 512; g0.N = 512; g0.K = 512;
            g0.gx = 8; g0.gy = 8; g0.gz = 8;
            n0 = 8 * 8 * 8;
            r0.dst = nxt; r0.part = pS; r0.len = 512 * 512; r0.nz = 8;
            r0.slab = 512 * 512; r0.Add = nullptr; r0.colMajor = 0;
            c0 = r0.len / 4;
        }

        // piece 1: combine w_m = A_k v_{2m} + v_{2m+1}
        {
            int sk = (n >= 1024) ? 1 : (n >= 512) ? 2 : (n >= 128) ? 4 : 8;
            g1.A = Ak; g1.Ars = 512;
            g1.B = tin; g1.Bks = 1; g1.Bjs = 1024;
            g1.C = tout; g1.Cis = 1; g1.Cjs = 512;
            g1.M = 512; g1.N = n; g1.K = 512;
            g1.gx = (n + 63) / 64; g1.gy = 8; g1.gz = sk;
            n1 = g1.gx * 8 * sk;
            if (sk == 1) {
                g1.Add = tin + 512; g1.Adjs = 1024;
                g1.part = nullptr; g1.slab = 0;
            } else {
                g1.Add = nullptr;
                g1.part = pC; g1.slab = (long long)512 * n;
                r1.dst = tout; r1.part = pC; r1.len = 512 * n; r1.nz = sk;
                r1.slab = (long long)512 * n;
                r1.Add = tin + 512; r1.Adjs = 1024; r1.colMajor = 1;
                c1 = r1.len / 4;
            }
        }

        // piece 2: Q-chain stage j = k-1 for k in 1..4
        if (k >= 1 && k <= 4) {
            int j = k - 1;
            const float* Aq; const float* Bq; const float* Adq; float* Cq; int Nq;
            long long Bjq, Adjq;
            if (j == 0) { Aq = A; Bq = V + 2046 * 512; Bjq = -1024;
                          Adq = V + 2047 * 512; Adjq = -1024; Cq = Q0; Nq = 8; }
            else if (j == 1) { Aq = Ap + 0LL * 512 * 512; Bq = Q0 + 512; Bjq = 1024;
                               Adq = Q0; Adjq = 1024; Cq = Q1; Nq = 4; }
            else if (j == 2) { Aq = Ap + 1LL * 512 * 512; Bq = Q1 + 512; Bjq = 1024;
                               Adq = Q1; Adjq = 1024; Cq = Q0; Nq = 2; }
            else             { Aq = Ap + 2LL * 512 * 512; Bq = Q0 + 512; Bjq = 1024;
                               Adq = Q0; Adjq = 1024; Cq = Q1; Nq = 1; }
            g2.A = Aq; g2.Ars = 512;
            g2.B = Bq; g2.Bks = 1; g2.Bjs = Bjq;
            g2.Add = nullptr;
            g2.C = Cq; g2.Cis = 1; g2.Cjs = 512;
            g2.part = pQ; g2.slab = (long long)512 * Nq;
            g2.M = 512; g2.N = Nq; g2.K = 512;
            g2.gx = 1; g2.gy = 8; g2.gz = 8;
            n2 = 1 * 8 * 8;
            r2.dst = Cq; r2.part = pQ; r2.len = 512 * Nq; r2.nz = 8;
            r2.slab = (long long)512 * Nq;
            r2.Add = Adq; r2.Adjs = Adjq; r2.colMajor = 1;
            c2 = r2.len / 4;
        }

        fused3_kernel<<<n0 + n1 + n2, 256>>>(g0, g1, g2, n0, n1);
        int ctot = c0 + c1 + c2;
        if (ctot > 0)
            fusedred_kernel<<<(ctot + 255) / 256, 256>>>(r0, r1, r2, c0, c1, c2);

        if (k < 10) Ak = Ap + (long long)k * (512 * 512);
        tin = tout;
        tout = (tout == T0) ? T1 : T0;
        n >>= 1;
    }
    const float* sv = tin;   // final state s (512)

    // ---- tail: y_nat = y_last - C s ; pred = y_last + C (q - s) ----
    ynat_pred_kernel<<<512, 128>>>(Cm, yh + 2047 * 256, sv, Q1, out);
}

// round 7
// speedup vs baseline: 6.7815x; 1.2015x over previous
#include <cuda_runtime.h>

// ---------------- scratch (static device globals; no allocation) ----------------
__device__ float g_T0[512 * 512];        // tree ping (1 MB)
__device__ float g_T1[512 * 512];        // tree pong (1 MB)
__device__ float g_Apow[10 * 512 * 512]; // A^2 .. A^1024 (10 MB)
__device__ float g_Bcat[4 * 512 * 256];  // [B | AB | A^2B | A^3B] (2 MB)
__device__ float g_Q[512];
__device__ float g_S[17 * 24 * 256];
__device__ float g_wv[306 * 256];
__device__ float g_pS[4 * 512 * 512];    // split-K partials: squarings (4 MB)
__device__ float g_pC[8 * 512 * 512];    // split-K partials: combines/cat/AB (8 MB)
__device__ float g_pD[4 * 512 * 256];    // split-K partials: A^3B (2 MB)

// ================= GEMM descriptor + device tile routine =========================
// Tile 128x64, 256 threads, 8x4 microtile, double-buffered, kk=16.
struct GemmDesc {
    const float* A; long long Ars; int Amode;      // 0: A[m*Ars+k]; 1: cat4 blocks [(k>>8)*131072 + m*256 + (k&255)]
    const float* B; long long Bks; long long Bjs;
    int Bmode;                                     // 0: B[k + n*Bjs]; 1: B[k*Bks + n]; 2: Ucat from u_history
    float* C; long long Cis; long long Cjs;
    float* part; long long slab;
    int M, N, K, gx, gy, gz;
};

__device__ __forceinline__ void gemm_block(const GemmDesc& d, int r)
{
    __shared__ float As[2][16][132];
    __shared__ float Bs[2][16][72];

    const int tid = threadIdx.x;
    const int bx = r % d.gx;
    const int by = (r / d.gx) % d.gy;
    const int z  = r / (d.gx * d.gy);
    const int bm = by * 128;
    const int bn = bx * 64;
    const int Kc = d.K / d.gz;
    const int kbeg = z * Kc;
    const int nt = Kc >> 4;

    const int arow = tid >> 1;          // 0..127
    const int akq  = (tid & 1) * 8;     // 0 or 8
    const int btn  = tid >> 2;          // 0..63  (Bmode 0/2)
    const int btk  = (tid & 3) * 4;     // 0..12
    const int bkk  = tid >> 4;          // 0..15  (Bmode 1)
    const int bn4  = (tid & 15) * 4;    // 0..60
    const int ty = tid >> 4, tx = tid & 15;

    float4 ax, ay, bv;

    auto loadA8 = [&](int kt) {
        int k = kbeg + kt + akq;
        const float* p = (d.Amode == 0)
            ? d.A + (long long)(bm + arow) * d.Ars + k
            : d.A + (long long)(k >> 8) * 131072 + (long long)(bm + arow) * 256 + (k & 255);
        ax = *(const float4*)p;
        ay = *(const float4*)(p + 4);
    };
    auto loadB4 = [&](int kt) {
        if (d.Bmode == 1) {
            bv = *(const float4*)(d.B + (long long)(kbeg + kt + bkk) * d.Bks + bn + bn4);
        } else if (d.Bmode == 0) {
            int n = bn + btn;
            bv = (n < d.N) ? *(const float4*)(d.B + (long long)(kbeg + kt + btk)
                                                + (long long)n * d.Bjs)
                           : make_float4(0.f, 0.f, 0.f, 0.f);
        } else { // Ucat: B = u_history; elem[k][n] = u[(2047-4n-(k>>8))*256 + (k&255)]
            int n = bn + btn;
            int k = kbeg + kt + btk;
            if (n < d.N) {
                int tu = 2047 - 4 * n - (k >> 8);
                bv = *(const float4*)(d.B + (long long)tu * 256 + (k & 255));
            } else bv = make_float4(0.f, 0.f, 0.f, 0.f);
        }
    };
    auto stAB = [&](int buf) {
        float av[8] = {ax.x, ax.y, ax.z, ax.w, ay.x, ay.y, ay.z, ay.w};
        #pragma unroll
        for (int j = 0; j < 8; j++) As[buf][akq + j][arow] = av[j];
        if (d.Bmode == 1) {
            *(float4*)&Bs[buf][bkk][bn4] = bv;
        } else {
            float vv[4] = {bv.x, bv.y, bv.z, bv.w};
            #pragma unroll
            for (int j = 0; j < 4; j++) Bs[buf][btk + j][btn] = vv[j];
        }
    };

    loadA8(0); loadB4(0);
    stAB(0);
    __syncthreads();

    float acc[8][4] = {};

    for (int t = 0; t < nt; t++) {
        int cur = t & 1;
        if (t + 1 < nt) { loadA8((t + 1) * 16); loadB4((t + 1) * 16); }
        #pragma unroll
        for (int kk = 0; kk < 16; kk++) {
            float4 a4 = *(const float4*)&As[cur][kk][ty * 8];
            float4 a5 = *(const float4*)&As[cur][kk][ty * 8 + 4];
            float4 b4 = *(const float4*)&Bs[cur][kk][tx * 4];
            float av[8] = {a4.x, a4.y, a4.z, a4.w, a5.x, a5.y, a5.z, a5.w};
            float bw[4] = {b4.x, b4.y, b4.z, b4.w};
            #pragma unroll
            for (int i = 0; i < 8; i++)
                #pragma unroll
                for (int j = 0; j < 4; j++)
                    acc[i][j] = fmaf(av[i], bw[j], acc[i][j]);
        }
        if (t + 1 < nt) {
            __syncthreads();
            stAB(cur ^ 1);
            __syncthreads();
        }
    }

    float* outp = d.part ? d.part + (long long)z * d.slab : d.C;
    if (d.Cjs == 1) {          // row-major (n-unit); N multiple of 4 at call sites
        int gn = bn + tx * 4;
        if (gn < d.N) {
            #pragma unroll
            for (int i = 0; i < 8; i++) {
                int gm = bm + ty * 8 + i;
                *(float4*)(outp + (long long)gm * d.Cis + gn) =
                    make_float4(acc[i][0], acc[i][1], acc[i][2], acc[i][3]);
            }
        }
    } else {                   // col-major (m-unit)
        #pragma unroll
        for (int j = 0; j < 4; j++) {
            int gn = bn + tx * 4 + j;
            if (gn < d.N) {
                long long base = (long long)(bm + ty * 8) + (long long)gn * d.Cjs;
                *(float4*)(outp + base)     = make_float4(acc[0][j], acc[1][j], acc[2][j], acc[3][j]);
                *(float4*)(outp + base + 4) = make_float4(acc[4][j], acc[5][j], acc[6][j], acc[7][j]);
            }
        }
    }
}

// ---------------- ut block (device): 80 MB HBM-bound matvec ----------------------
__device__ __forceinline__ void ut_block(const float* __restrict__ Mm,
                                         const float* __restrict__ Mbar,
                                         const float* __restrict__ wv,
                                         float* __restrict__ out, int n)
{
    int p = threadIdx.x;
    float acc = 0.f;
    #pragma unroll 4
    for (int b = 0; b < 17; b++)
        acc += Mbar[((long long)b * 256 + n) * 256 + p] * wv[b * 256 + p];
    #pragma unroll 4
    for (int bb = 0; bb < 289; bb++)
        acc += Mm[((long long)bb * 256 + n) * 256 + p] * wv[(17 + bb) * 256 + p];
    __shared__ float sd[256];
    sd[p] = acc;
    __syncthreads();
    for (int st = 128; st > 0; st >>= 1) {
        if (p < st) sd[p] += sd[p + st];
        __syncthreads();
    }
    if (p == 0) out[512 + n] = sd[0];
}

// -------- fused launch: optional ut blocks + up to 3 GEMM pieces -----------------
__global__ __launch_bounds__(256)
void mega_kernel(GemmDesc d0, GemmDesc d1, GemmDesc d2, int n0, int n1, int nu,
                 const float* Mm, const float* Mbar, const float* wv, float* out)
{
    int b = blockIdx.x;
    if (b < nu) { ut_block(Mm, Mbar, wv, out, b); return; }
    b -= nu;
    if (b < n0)            gemm_block(d0, b);
    else if (b < n0 + n1)  gemm_block(d1, b - n0);
    else                   gemm_block(d2, b - n0 - n1);
}

// ================= fused split-K reduce ==========================================
struct RedDesc {
    float* dst; const float* part;
    int len; int nz; long long slab;
    const float* Add; long long Adjs; int colMajor;
};

__device__ __forceinline__ void red_elem(const RedDesc& r, int g)
{
    int i = g * 4;
    float4 acc = *(const float4*)(r.part + i);
    for (int zz = 1; zz < r.nz; zz++) {
        float4 v = *(const float4*)(r.part + (long long)zz * r.slab + i);
        acc.x += v.x; acc.y += v.y; acc.z += v.z; acc.w += v.w;
    }
    if (r.Add && r.colMajor) {
        int gm = i & 511, gn = i >> 9;
        const float* ap = r.Add + gm + (long long)gn * r.Adjs;
        acc.x += ap[0]; acc.y += ap[1]; acc.z += ap[2]; acc.w += ap[3];
    }
    *(float4*)(r.dst + i) = acc;
}

__global__ __launch_bounds__(256)
void fusedred_kernel(RedDesc r0, RedDesc r1, RedDesc r2, int c0, int c1, int c2)
{
    int g = blockIdx.x * 256 + threadIdx.x;
    if (g < c0)                 red_elem(r0, g);
    else if (g < c0 + c1)       red_elem(r1, g - c0);
    else if (g < c0 + c1 + c2)  red_elem(r2, g - c0 - c1);
}

// ---------------- controller prep ------------------------------------------------
__global__ void s_kernel(const float* __restrict__ phi, const float* __restrict__ ynh,
                         float* __restrict__ S)
{
    int l = blockIdx.x / 24, j = blockIdx.x % 24, p = threadIdx.x;
    float acc = 0.f;
    #pragma unroll
    for (int k = 0; k < 25; k++)
        acc += phi[k * 17 + l] * ynh[(2047 - (2 + j + k)) * 256 + p];
    S[blockIdx.x * 256 + p] = acc;
}

__global__ void wv_kernel(const float* __restrict__ ynh, const float* __restrict__ S,
                          const float* __restrict__ phi, const float* __restrict__ phit,
                          const float* __restrict__ sig, const float* __restrict__ lam,
                          float* __restrict__ wv)
{
    int b = blockIdx.x, p = threadIdx.x;
    float v;
    if (b == 0) {
        v = ynh[2047 * 256 + p];
    } else if (b < 17) {
        int i = b - 1;
        float lam4 = sqrtf(sqrtf(lam[i]));
        float acc = 0.f;
        #pragma unroll
        for (int j = 0; j < 24; j++)
            acc += phit[j * 16 + i] * ynh[(2047 - 1 - j) * 256 + p];
        v = lam4 * acc;
    } else {
        int bb = b - 17, ip = bb / 17, l = bb % 17;
        float s4 = sqrtf(sqrtf(sig[l]));
        if (ip == 0) {
            float acc = 0.f;
            #pragma unroll
            for (int k = 0; k < 25; k++)
                acc += phi[k * 17 + l] * ynh[(2047 - k) * 256 + p];
            v = s4 * acc;
        } else {
            int i = ip - 1;
            float lam4 = sqrtf(sqrtf(lam[i]));
            float acc = 0.f;
            #pragma unroll
            for (int j = 0; j < 24; j++)
                acc += phit[j * 16 + i] * S[(l * 24 + j) * 256 + p];
            v = lam4 * s4 * acc;
        }
    }
    wv[b * 256 + p] = v;
}

// ---------------- y_nat / pred ---------------------------------------------------
__global__ void ynat_pred_kernel(const float* __restrict__ Cm, const float* __restrict__ ylast,
                                 const float* __restrict__ s, const float* __restrict__ q,
                                 float* __restrict__ out)
{
    int row = blockIdx.x;
    int p = row & 255;
    bool isPred = row >= 256;
    const float* cr = Cm + p * 512;
    float acc = 0.f;
    for (int d = threadIdx.x; d < 512; d += 128) {
        float x = isPred ? (q[d] - s[d]) : (-s[d]);
        acc += cr[d] * x;
    }
    __shared__ float sd[128];
    sd[threadIdx.x] = acc;
    __syncthreads();
    for (int st = 64; st > 0; st >>= 1) {
        if (threadIdx.x < st) sd[threadIdx.x] += sd[threadIdx.x + st];
        __syncthreads();
    }
    if (threadIdx.x == 0) out[row] = ylast[p] + sd[0];
}

// =================================================================================
extern "C" void kernel_launch(void* const* d_in, const int* in_sizes, int n_in,
                              void* d_out, int out_size)
{
    const float* A    = (const float*)d_in[0];
    const float* Bm   = (const float*)d_in[1];
    const float* Cm   = (const float*)d_in[2];
    const float* Mm   = (const float*)d_in[3];
    const float* Mbar = (const float*)d_in[4];
    const float* sig  = (const float*)d_in[5];
    const float* phi  = (const float*)d_in[6];
    const float* lam  = (const float*)d_in[7];
    const float* phit = (const float*)d_in[8];
    const float* yh   = (const float*)d_in[9];
    const float* uh   = (const float*)d_in[10];
    const float* ynh  = (const float*)d_in[11];
    float* out = (float*)d_out;

    float *T0, *T1, *Ap, *Bc, *Qb, *S, *wv, *pS, *pC, *pD;
    cudaGetSymbolAddress((void**)&T0, g_T0);
    cudaGetSymbolAddress((void**)&T1, g_T1);
    cudaGetSymbolAddress((void**)&Ap, g_Apow);
    cudaGetSymbolAddress((void**)&Bc, g_Bcat);
    cudaGetSymbolAddress((void**)&Qb, g_Q);
    cudaGetSymbolAddress((void**)&S,  g_S);
    cudaGetSymbolAddress((void**)&wv, g_wv);
    cudaGetSymbolAddress((void**)&pS, g_pS);
    cudaGetSymbolAddress((void**)&pC, g_pC);
    cudaGetSymbolAddress((void**)&pD, g_pD);

    const long long SQ = 512 * 512;  // 262144
    const long long HB = 512 * 256;  // 131072

    GemmDesc gd = {}; gd.gx = gd.gy = gd.gz = 1;   // dummy
    RedDesc  rd = {};

    auto sqDesc = [&](int k) {       // Ap[k] = Ak^2, Ak = (k==0 ? A : Ap[k-1])
        GemmDesc d = gd;
        const float* src = (k == 0) ? A : Ap + (long long)(k - 1) * SQ;
        d.A = src; d.Ars = 512; d.Amode = 0;
        d.B = src; d.Bks = 512; d.Bmode = 1;
        d.C = Ap + (long long)k * SQ; d.Cis = 512; d.Cjs = 1;
        d.part = pS; d.slab = SQ;
        d.M = 512; d.N = 512; d.K = 512; d.gx = 8; d.gy = 4; d.gz = 4;
        return d;
    };
    auto sqRed = [&](int k) {
        RedDesc r = rd;
        r.dst = Ap + (long long)k * SQ; r.part = pS;
        r.len = (int)SQ; r.nz = 4; r.slab = SQ;
        return r;
    };

    // ---- prep ----
    s_kernel<<<17 * 24, 256>>>(phi, ynh, S);
    wv_kernel<<<306, 256>>>(ynh, S, phi, phit, sig, lam, wv);
    cudaMemcpyAsync(Bc, Bm, HB * sizeof(float), cudaMemcpyDeviceToDevice);

    // ---- F1: ut (256) | AB = A*B (64) | sq0 (128) ----
    {
        GemmDesc dAB = gd;
        dAB.A = A; dAB.Ars = 512; dAB.Amode = 0;
        dAB.B = Bm; dAB.Bks = 256; dAB.Bmode = 1;
        dAB.C = Bc + HB; dAB.Cis = 256; dAB.Cjs = 1;
        dAB.part = pC; dAB.slab = HB;
        dAB.M = 512; dAB.N = 256; dAB.K = 512; dAB.gx = 4; dAB.gy = 4; dAB.gz = 4;
        GemmDesc dS0 = sqDesc(0);
        mega_kernel<<<256 + 64 + 128, 256>>>(dAB, dS0, gd, 64, 128, 256, Mm, Mbar, wv, out);

        RedDesc rAB = rd; rAB.dst = Bc + HB; rAB.part = pC; rAB.len = (int)HB; rAB.nz = 4; rAB.slab = HB;
        RedDesc rS0 = sqRed(0);
        int c0 = (int)HB / 4, c1 = (int)SQ / 4;
        fusedred_kernel<<<(c0 + c1 + 255) / 256, 256>>>(rAB, rS0, rd, c0, c1, 0);
    }

    // ---- F2: A^2B | A^3B | sq1 ----
    {
        GemmDesc d2 = gd;
        d2.A = Ap; d2.Ars = 512; d2.Amode = 0;
        d2.B = Bm; d2.Bks = 256; d2.Bmode = 1;
        d2.C = Bc + 2 * HB; d2.Cis = 256; d2.Cjs = 1;
        d2.part = pC; d2.slab = HB;
        d2.M = 512; d2.N = 256; d2.K = 512; d2.gx = 4; d2.gy = 4; d2.gz = 4;
        GemmDesc d3 = d2;
        d3.B = Bc + HB;            // AB
        d3.C = Bc + 3 * HB;
        d3.part = pD;
        GemmDesc dS1 = sqDesc(1);
        mega_kernel<<<64 + 64 + 128, 256>>>(d2, d3, dS1, 64, 64, 0, Mm, Mbar, wv, out);

        RedDesc r2 = rd; r2.dst = Bc + 2 * HB; r2.part = pC; r2.len = (int)HB; r2.nz = 4; r2.slab = HB;
        RedDesc r3 = rd; r3.dst = Bc + 3 * HB; r3.part = pD; r3.len = (int)HB; r3.nz = 4; r3.slab = HB;
        RedDesc rS1 = sqRed(1);
        int c0 = (int)HB / 4, c2 = (int)SQ / 4;
        fusedred_kernel<<<(c0 + c0 + c2 + 255) / 256, 256>>>(r2, r3, rS1, c0, c0, c2);
    }

    // ---- F3: W = Bcat x Ucat (128) | sq2 (128) ----
    {
        GemmDesc dW = gd;
        dW.A = Bc; dW.Amode = 1;
        dW.B = uh; dW.Bmode = 2;
        dW.C = T0; dW.Cis = 1; dW.Cjs = 512;
        dW.part = pC; dW.slab = SQ;
        dW.M = 512; dW.N = 512; dW.K = 1024; dW.gx = 8; dW.gy = 4; dW.gz = 4;
        GemmDesc dS2 = sqDesc(2);
        mega_kernel<<<128 + 128, 256>>>(dW, dS2, gd, 128, 128, 0, Mm, Mbar, wv, out);

        RedDesc rW = rd; rW.dst = T0; rW.part = pC; rW.len = (int)SQ; rW.nz = 4; rW.slab = SQ;
        RedDesc rS2 = sqRed(2);
        int c = (int)SQ / 4;
        fusedred_kernel<<<(2 * c + 255) / 256, 256>>>(rW, rS2, rd, c, c, 0);
    }

    // ---- tree levels k=0..8: X^{k+1}_m = X^k_{2m} + A^(2^(k+2)) X^k_{2m+1} ----
    float* bin = T0;
    float* bout = T1;
    for (int k = 0; k < 9; k++) {
        int Nk = 256 >> k;
        GemmDesc dL = gd;
        dL.A = Ap + (long long)(k + 1) * SQ; dL.Ars = 512; dL.Amode = 0;
        dL.B = bin + 512; dL.Bks = 1; dL.Bjs = 1024; dL.Bmode = 0;
        dL.C = bout; dL.Cis = 1; dL.Cjs = 512;
        dL.part = pC; dL.slab = (long long)512 * Nk;
        dL.M = 512; dL.N = Nk; dL.K = 512;
        dL.gx = (Nk + 63) / 64; dL.gy = 4; dL.gz = 8;
        int nL = dL.gx * 4 * 8;

        RedDesc rL = rd;
        rL.dst = bout; rL.part = pC; rL.len = 512 * Nk; rL.nz = 8; rL.slab = (long long)512 * Nk;
        rL.Add = bin; rL.Adjs = 1024; rL.colMajor = 1;
        int cL = rL.len / 4;

        if (k <= 6) {
            GemmDesc dSq = sqDesc(k + 3);
            mega_kernel<<<nL + 128, 256>>>(dL, dSq, gd, nL, 128, 0, Mm, Mbar, wv, out);
            RedDesc rSq = sqRed(k + 3);
            int cS = (int)SQ / 4;
            fusedred_kernel<<<(cL + cS + 255) / 256, 256>>>(rL, rSq, rd, cL, cS, 0);
        } else {
            mega_kernel<<<nL, 256>>>(dL, gd, gd, nL, 0, 0, Mm, Mbar, wv, out);
            fusedred_kernel<<<(cL + 255) / 256, 256>>>(rL, rd, rd, cL, 0, 0);
        }

        if (k == 1)   // q = X^2 column 0
            cudaMemcpyAsync(Qb, bout, 512 * sizeof(float), cudaMemcpyDeviceToDevice);

        float* tmp = bin; bin = bout; bout = tmp;
    }
    const float* sv = bin;   // s = X^9 column 0

    // ---- tail: y_nat = y_last - C s ; pred = y_last + C (q - s) ----
    ynat_pred_kernel<<<512, 128>>>(Cm, yh + 2047 * 256, sv, Qb, out);
}

// round 9
// speedup vs baseline: 7.5646x; 1.1155x over previous
#include <cuda_runtime.h>

// ---------------- scratch (static device globals; no allocation) ----------------
__device__ float g_T0[512 * 512];        // tree ping (1 MB)
__device__ float g_T1[512 * 512];        // tree pong (1 MB)
__device__ float g_Apow[10 * 512 * 512]; // A^2 .. A^1024 (10 MB)
__device__ float g_Bcat[4 * 512 * 256];  // [B | AB | A^2B | A^3B] (2 MB)
__device__ float g_Q[512];
__device__ float g_S[17 * 24 * 256];
__device__ float g_wv[306 * 256];
__device__ float g_pS[8 * 512 * 512];    // split-K partials: squarings (8 MB)
__device__ float g_pC[8 * 512 * 512];    // split-K partials: combines/cat/AB (8 MB)
__device__ float g_pD[8 * 512 * 256];    // split-K partials: A^3B (4 MB)

// ================= GEMM descriptor + device tile routine =========================
// Tile 128x64, 256 threads, 8x4 microtile, double-buffered, kk=16.
struct GemmDesc {
    const float* A; long long Ars; int Amode;      // 0: A[m*Ars+k]; 1: cat4 blocks [(k>>8)*131072 + m*256 + (k&255)]
    const float* B; long long Bks; long long Bjs;
    int Bmode;                                     // 0: B[k + n*Bjs]; 1: B[k*Bks + n]; 2: Ucat from u_history
    float* C; long long Cis; long long Cjs;
    float* part; long long slab;
    int M, N, K, gx, gy, gz;
};

__device__ __forceinline__ void gemm_block(const GemmDesc& d, int r)
{
    __shared__ float As[2][16][132];
    __shared__ float Bs[2][16][72];

    const int tid = threadIdx.x;
    const int bx = r % d.gx;
    const int by = (r / d.gx) % d.gy;
    const int z  = r / (d.gx * d.gy);
    const int bm = by * 128;
    const int bn = bx * 64;
    const int Kc = d.K / d.gz;
    const int kbeg = z * Kc;
    const int nt = Kc >> 4;

    const int arow = tid >> 1;          // 0..127
    const int akq  = (tid & 1) * 8;     // 0 or 8
    const int btn  = tid >> 2;          // 0..63  (Bmode 0/2)
    const int btk  = (tid & 3) * 4;     // 0..12
    const int bkk  = tid >> 4;          // 0..15  (Bmode 1)
    const int bn4  = (tid & 15) * 4;    // 0..60
    const int ty = tid >> 4, tx = tid & 15;

    float4 ax, ay, bv;

    auto loadA8 = [&](int kt) {
        int k = kbeg + kt + akq;
        const float* p = (d.Amode == 0)
            ? d.A + (long long)(bm + arow) * d.Ars + k
            : d.A + (long long)(k >> 8) * 131072 + (long long)(bm + arow) * 256 + (k & 255);
        ax = *(const float4*)p;
        ay = *(const float4*)(p + 4);
    };
    auto loadB4 = [&](int kt) {
        if (d.Bmode == 1) {
            bv = *(const float4*)(d.B + (long long)(kbeg + kt + bkk) * d.Bks + bn + bn4);
        } else if (d.Bmode == 0) {
            int n = bn + btn;
            bv = (n < d.N) ? *(const float4*)(d.B + (long long)(kbeg + kt + btk)
                                                + (long long)n * d.Bjs)
                           : make_float4(0.f, 0.f, 0.f, 0.f);
        } else { // Ucat: B = u_history; elem[k][n] = u[(2047-4n-(k>>8))*256 + (k&255)]
            int n = bn + btn;
            int k = kbeg + kt + btk;
            if (n < d.N) {
                int tu = 2047 - 4 * n - (k >> 8);
                bv = *(const float4*)(d.B + (long long)tu * 256 + (k & 255));
            } else bv = make_float4(0.f, 0.f, 0.f, 0.f);
        }
    };
    auto stAB = [&](int buf) {
        float av[8] = {ax.x, ax.y, ax.z, ax.w, ay.x, ay.y, ay.z, ay.w};
        #pragma unroll
        for (int j = 0; j < 8; j++) As[buf][akq + j][arow] = av[j];
        if (d.Bmode == 1) {
            *(float4*)&Bs[buf][bkk][bn4] = bv;
        } else {
            float vv[4] = {bv.x, bv.y, bv.z, bv.w};
            #pragma unroll
            for (int j = 0; j < 4; j++) Bs[buf][btk + j][btn] = vv[j];
        }
    };

    loadA8(0); loadB4(0);
    stAB(0);
    __syncthreads();

    float acc[8][4] = {};

    for (int t = 0; t < nt; t++) {
        int cur = t & 1;
        if (t + 1 < nt) { loadA8((t + 1) * 16); loadB4((t + 1) * 16); }
        #pragma unroll
        for (int kk = 0; kk < 16; kk++) {
            float4 a4 = *(const float4*)&As[cur][kk][ty * 8];
            float4 a5 = *(const float4*)&As[cur][kk][ty * 8 + 4];
            float4 b4 = *(const float4*)&Bs[cur][kk][tx * 4];
            float av[8] = {a4.x, a4.y, a4.z, a4.w, a5.x, a5.y, a5.z, a5.w};
            float bw[4] = {b4.x, b4.y, b4.z, b4.w};
            #pragma unroll
            for (int i = 0; i < 8; i++)
                #pragma unroll
                for (int j = 0; j < 4; j++)
                    acc[i][j] = fmaf(av[i], bw[j], acc[i][j]);
        }
        if (t + 1 < nt) {
            __syncthreads();
            stAB(cur ^ 1);
            __syncthreads();
        }
    }

    float* outp = d.part ? d.part + (long long)z * d.slab : d.C;
    if (d.Cjs == 1) {          // row-major (n-unit); N multiple of 4 at call sites
        int gn = bn + tx * 4;
        if (gn < d.N) {
            #pragma unroll
            for (int i = 0; i < 8; i++) {
                int gm = bm + ty * 8 + i;
                *(float4*)(outp + (long long)gm * d.Cis + gn) =
                    make_float4(acc[i][0], acc[i][1], acc[i][2], acc[i][3]);
            }
        }
    } else {                   // col-major (m-unit)
        #pragma unroll
        for (int j = 0; j < 4; j++) {
            int gn = bn + tx * 4 + j;
            if (gn < d.N) {
                long long base = (long long)(bm + ty * 8) + (long long)gn * d.Cjs;
                *(float4*)(outp + base)     = make_float4(acc[0][j], acc[1][j], acc[2][j], acc[3][j]);
                *(float4*)(outp + base + 4) = make_float4(acc[4][j], acc[5][j], acc[6][j], acc[7][j]);
            }
        }
    }
}

// ---------------- ut block (device): 80 MB HBM-bound matvec ----------------------
__device__ __forceinline__ void ut_block(const float* __restrict__ Mm,
                                         const float* __restrict__ Mbar,
                                         const float* __restrict__ wv,
                                         float* __restrict__ out, int n)
{
    int p = threadIdx.x;
    float acc = 0.f;
    #pragma unroll 4
    for (int b = 0; b < 17; b++)
        acc += Mbar[((long long)b * 256 + n) * 256 + p] * wv[b * 256 + p];
    #pragma unroll 4
    for (int bb = 0; bb < 289; bb++)
        acc += Mm[((long long)bb * 256 + n) * 256 + p] * wv[(17 + bb) * 256 + p];
    __shared__ float sd[256];
    sd[p] = acc;
    __syncthreads();
    for (int st = 128; st > 0; st >>= 1) {
        if (p < st) sd[p] += sd[p + st];
        __syncthreads();
    }
    if (p == 0) out[512 + n] = sd[0];
}

// -------- fused launch: optional ut blocks + up to 3 GEMM pieces -----------------
__global__ __launch_bounds__(256)
void mega_kernel(GemmDesc d0, GemmDesc d1, GemmDesc d2, int n0, int n1, int nu,
                 const float* Mm, const float* Mbar, const float* wv, float* out)
{
    int b = blockIdx.x;
    if (b < nu) { ut_block(Mm, Mbar, wv, out, b); return; }
    b -= nu;
    if (b < n0)            gemm_block(d0, b);
    else if (b < n0 + n1)  gemm_block(d1, b - n0);
    else                   gemm_block(d2, b - n0 - n1);
}

// ================= fused split-K reduce ==========================================
struct RedDesc {
    float* dst; const float* part;
    int len; int nz; long long slab;
    const float* Add; long long Adjs; int colMajor;
};

__device__ __forceinline__ void red_elem(const RedDesc& r, int g)
{
    int i = g * 4;
    float4 acc;
    if (r.nz == 8) {
        // MLP-8 fast path: all partial loads issued before any accumulation
        float4 v[8];
        #pragma unroll
        for (int zz = 0; zz < 8; zz++)
            v[zz] = *(const float4*)(r.part + (long long)zz * r.slab + i);
        acc = v[0];
        #pragma unroll
        for (int zz = 1; zz < 8; zz++) {
            acc.x += v[zz].x; acc.y += v[zz].y; acc.z += v[zz].z; acc.w += v[zz].w;
        }
    } else {
        acc = *(const float4*)(r.part + i);
        for (int zz = 1; zz < r.nz; zz++) {
            float4 v = *(const float4*)(r.part + (long long)zz * r.slab + i);
            acc.x += v.x; acc.y += v.y; acc.z += v.z; acc.w += v.w;
        }
    }
    if (r.Add && r.colMajor) {
        int gm = i & 511, gn = i >> 9;
        const float* ap = r.Add + gm + (long long)gn * r.Adjs;
        acc.x += ap[0]; acc.y += ap[1]; acc.z += ap[2]; acc.w += ap[3];
    }
    *(float4*)(r.dst + i) = acc;
}

__global__ __launch_bounds__(256)
void fusedred_kernel(RedDesc r0, RedDesc r1, RedDesc r2, int c0, int c1, int c2)
{
    int g = blockIdx.x * 256 + threadIdx.x;
    if (g < c0)                 red_elem(r0, g);
    else if (g < c0 + c1)       red_elem(r1, g - c0);
    else if (g < c0 + c1 + c2)  red_elem(r2, g - c0 - c1);
}

// ---------------- controller prep ------------------------------------------------
__global__ void s_kernel(const float* __restrict__ phi, const float* __restrict__ ynh,
                         float* __restrict__ S)
{
    int l = blockIdx.x / 24, j = blockIdx.x % 24, p = threadIdx.x;
    float acc = 0.f;
    #pragma unroll
    for (int k = 0; k < 25; k++)
        acc += phi[k * 17 + l] * ynh[(2047 - (2 + j + k)) * 256 + p];
    S[blockIdx.x * 256 + p] = acc;
}

__global__ void wv_kernel(const float* __restrict__ ynh, const float* __restrict__ S,
                          const float* __restrict__ phi, const float* __restrict__ phit,
                          const float* __restrict__ sig, const float* __restrict__ lam,
                          float* __restrict__ wv)
{
    int b = blockIdx.x, p = threadIdx.x;
    float v;
    if (b == 0) {
        v = ynh[2047 * 256 + p];
    } else if (b < 17) {
        int i = b - 1;
        float lam4 = sqrtf(sqrtf(lam[i]));
        float acc = 0.f;
        #pragma unroll
        for (int j = 0; j < 24; j++)
            acc += phit[j * 16 + i] * ynh[(2047 - 1 - j) * 256 + p];
        v = lam4 * acc;
    } else {
        int bb = b - 17, ip = bb / 17, l = bb % 17;
        float s4 = sqrtf(sqrtf(sig[l]));
        if (ip == 0) {
            float acc = 0.f;
            #pragma unroll
            for (int k = 0; k < 25; k++)
                acc += phi[k * 17 + l] * ynh[(2047 - k) * 256 + p];
            v = s4 * acc;
        } else {
            int i = ip - 1;
            float lam4 = sqrtf(sqrtf(lam[i]));
            float acc = 0.f;
            #pragma unroll
            for (int j = 0; j < 24; j++)
                acc += phit[j * 16 + i] * S[(l * 24 + j) * 256 + p];
            v = lam4 * s4 * acc;
        }
    }
    wv[b * 256 + p] = v;
}

// ---------------- y_nat / pred ---------------------------------------------------
__global__ void ynat_pred_kernel(const float* __restrict__ Cm, const float* __restrict__ ylast,
                                 const float* __restrict__ s, const float* __restrict__ q,
                                 float* __restrict__ out)
{
    int row = blockIdx.x;
    int p = row & 255;
    bool isPred = row >= 256;
    const float* cr = Cm + p * 512;
    float acc = 0.f;
    for (int d = threadIdx.x; d < 512; d += 128) {
        float x = isPred ? (q[d] - s[d]) : (-s[d]);
        acc += cr[d] * x;
    }
    __shared__ float sd[128];
    sd[threadIdx.x] = acc;
    __syncthreads();
    for (int st = 64; st > 0; st >>= 1) {
        if (threadIdx.x < st) sd[threadIdx.x] += sd[threadIdx.x + st];
        __syncthreads();
    }
    if (threadIdx.x == 0) out[row] = ylast[p] + sd[0];
}

// =================================================================================
extern "C" void kernel_launch(void* const* d_in, const int* in_sizes, int n_in,
                              void* d_out, int out_size)
{
    const float* A    = (const float*)d_in[0];
    const float* Bm   = (const float*)d_in[1];
    const float* Cm   = (const float*)d_in[2];
    const float* Mm   = (const float*)d_in[3];
    const float* Mbar = (const float*)d_in[4];
    const float* sig  = (const float*)d_in[5];
    const float* phi  = (const float*)d_in[6];
    const float* lam  = (const float*)d_in[7];
    const float* phit = (const float*)d_in[8];
    const float* yh   = (const float*)d_in[9];
    const float* uh   = (const float*)d_in[10];
    const float* ynh  = (const float*)d_in[11];
    float* out = (float*)d_out;

    float *T0, *T1, *Ap, *Bc, *Qb, *S, *wv, *pS, *pC, *pD;
    cudaGetSymbolAddress((void**)&T0, g_T0);
    cudaGetSymbolAddress((void**)&T1, g_T1);
    cudaGetSymbolAddress((void**)&Ap, g_Apow);
    cudaGetSymbolAddress((void**)&Bc, g_Bcat);
    cudaGetSymbolAddress((void**)&Qb, g_Q);
    cudaGetSymbolAddress((void**)&S,  g_S);
    cudaGetSymbolAddress((void**)&wv, g_wv);
    cudaGetSymbolAddress((void**)&pS, g_pS);
    cudaGetSymbolAddress((void**)&pC, g_pC);
    cudaGetSymbolAddress((void**)&pD, g_pD);

    const long long SQ = 512 * 512;  // 262144
    const long long HB = 512 * 256;  // 131072

    GemmDesc gd = {}; gd.gx = gd.gy = gd.gz = 1;   // dummy
    RedDesc  rd = {};

    auto sqDesc = [&](int k) {       // Ap[k] = Ak^2, Ak = (k==0 ? A : Ap[k-1])
        GemmDesc d = gd;
        const float* src = (k == 0) ? A : Ap + (long long)(k - 1) * SQ;
        d.A = src; d.Ars = 512; d.Amode = 0;
        d.B = src; d.Bks = 512; d.Bmode = 1;
        d.C = Ap + (long long)k * SQ; d.Cis = 512; d.Cjs = 1;
        d.part = pS; d.slab = SQ;
        d.M = 512; d.N = 512; d.K = 512; d.gx = 8; d.gy = 4; d.gz = 8;
        return d;
    };
    auto sqRed = [&](int k) {
        RedDesc r = rd;
        r.dst = Ap + (long long)k * SQ; r.part = pS;
        r.len = (int)SQ; r.nz = 8; r.slab = SQ;
        return r;
    };

    // ---- prep ----
    s_kernel<<<17 * 24, 256>>>(phi, ynh, S);
    wv_kernel<<<306, 256>>>(ynh, S, phi, phit, sig, lam, wv);
    cudaMemcpyAsync(Bc, Bm, HB * sizeof(float), cudaMemcpyDeviceToDevice);

    // ---- F1: ut (256) | AB = A*B (128) | sq0 (256) ----
    {
        GemmDesc dAB = gd;
        dAB.A = A; dAB.Ars = 512; dAB.Amode = 0;
        dAB.B = Bm; dAB.Bks = 256; dAB.Bmode = 1;
        dAB.C = Bc + HB; dAB.Cis = 256; dAB.Cjs = 1;
        dAB.part = pC; dAB.slab = HB;
        dAB.M = 512; dAB.N = 256; dAB.K = 512; dAB.gx = 4; dAB.gy = 4; dAB.gz = 8;
        GemmDesc dS0 = sqDesc(0);
        mega_kernel<<<256 + 128 + 256, 256>>>(dAB, dS0, gd, 128, 256, 256, Mm, Mbar, wv, out);

        RedDesc rAB = rd; rAB.dst = Bc + HB; rAB.part = pC; rAB.len = (int)HB; rAB.nz = 8; rAB.slab = HB;
        RedDesc rS0 = sqRed(0);
        int c0 = (int)HB / 4, c1 = (int)SQ / 4;
        fusedred_kernel<<<(c0 + c1 + 255) / 256, 256>>>(rAB, rS0, rd, c0, c1, 0);
    }

    // ---- F2: A^2B | A^3B | sq1 ----
    {
        GemmDesc d2 = gd;
        d2.A = Ap; d2.Ars = 512; d2.Amode = 0;
        d2.B = Bm; d2.Bks = 256; d2.Bmode = 1;
        d2.C = Bc + 2 * HB; d2.Cis = 256; d2.Cjs = 1;
        d2.part = pC; d2.slab = HB;
        d2.M = 512; d2.N = 256; d2.K = 512; d2.gx = 4; d2.gy = 4; d2.gz = 8;
        GemmDesc d3 = d2;
        d3.B = Bc + HB;            // AB
        d3.C = Bc + 3 * HB;
        d3.part = pD;
        GemmDesc dS1 = sqDesc(1);
        mega_kernel<<<128 + 128 + 256, 256>>>(d2, d3, dS1, 128, 128, 0, Mm, Mbar, wv, out);

        RedDesc r2 = rd; r2.dst = Bc + 2 * HB; r2.part = pC; r2.len = (int)HB; r2.nz = 8; r2.slab = HB;
        RedDesc r3 = rd; r3.dst = Bc + 3 * HB; r3.part = pD; r3.len = (int)HB; r3.nz = 8; r3.slab = HB;
        RedDesc rS1 = sqRed(1);
        int c0 = (int)HB / 4, c2 = (int)SQ / 4;
        fusedred_kernel<<<(c0 + c0 + c2 + 255) / 256, 256>>>(r2, r3, rS1, c0, c0, c2);
    }

    // ---- F3: W = Bcat x Ucat (256) | sq2 (256) ----
    {
        GemmDesc dW = gd;
        dW.A = Bc; dW.Amode = 1;
        dW.B = uh; dW.Bmode = 2;
        dW.C = T0; dW.Cis = 1; dW.Cjs = 512;
        dW.part = pC; dW.slab = SQ;
        dW.M = 512; dW.N = 512; dW.K = 1024; dW.gx = 8; dW.gy = 4; dW.gz = 8;
        GemmDesc dS2 = sqDesc(2);
        mega_kernel<<<256 + 256, 256>>>(dW, dS2, gd, 256, 256, 0, Mm, Mbar, wv, out);

        RedDesc rW = rd; rW.dst = T0; rW.part = pC; rW.len = (int)SQ; rW.nz = 8; rW.slab = SQ;
        RedDesc rS2 = sqRed(2);
        int c = (int)SQ / 4;
        fusedred_kernel<<<(2 * c + 255) / 256, 256>>>(rW, rS2, rd, c, c, 0);
    }

    // ---- tree levels k=0..8: X^{k+1}_m = X^k_{2m} + A^(2^(k+2)) X^k_{2m+1} ----
    float* bin = T0;
    float* bout = T1;
    for (int k = 0; k < 9; k++) {
        int Nk = 256 >> k;
        GemmDesc dL = gd;
        dL.A = Ap + (long long)(k + 1) * SQ; dL.Ars = 512; dL.Amode = 0;
        dL.B = bin + 512; dL.Bks = 1; dL.Bjs = 1024; dL.Bmode = 0;
        dL.C = bout; dL.Cis = 1; dL.Cjs = 512;
        dL.part = pC; dL.slab = (long long)512 * Nk;
        dL.M = 512; dL.N = Nk; dL.K = 512;
        dL.gx = (Nk + 63) / 64; dL.gy = 4; dL.gz = 8;
        int nL = dL.gx * 4 * 8;

        RedDesc rL = rd;
        rL.dst = bout; rL.part = pC; rL.len = 512 * Nk; rL.nz = 8; rL.slab = (long long)512 * Nk;
        rL.Add = bin; rL.Adjs = 1024; rL.colMajor = 1;
        int cL = rL.len / 4;

        if (k <= 6) {
            GemmDesc dSq = sqDesc(k + 3);
            mega_kernel<<<nL + 256, 256>>>(dL, dSq, gd, nL, 256, 0, Mm, Mbar, wv, out);
            RedDesc rSq = sqRed(k + 3);
            int cS = (int)SQ / 4;
            fusedred_kernel<<<(cL + cS + 255) / 256, 256>>>(rL, rSq, rd, cL, cS, 0);
        } else {
            mega_kernel<<<nL, 256>>>(dL, gd, gd, nL, 0, 0, Mm, Mbar, wv, out);
            fusedred_kernel<<<(cL + 255) / 256, 256>>>(rL, rd, rd, cL, 0, 0);
        }

        if (k == 1)   // q = X^2 column 0
            cudaMemcpyAsync(Qb, bout, 512 * sizeof(float), cudaMemcpyDeviceToDevice);

        float* tmp = bin; bin = bout; bout = tmp;
    }
    const float* sv = bin;   // s = X^9 column 0

    // ---- tail: y_nat = y_last - C s ; pred = y_last + C (q - s) ----
    ynat_pred_kernel<<<512, 128>>>(Cm, yh + 2047 * 256, sv, Qb, out);
}